// round 4
// baseline (speedup 1.0000x reference)
#include <cuda_runtime.h>

// Problem constants
#define B_ROWS 64
#define N_COLS 262144
#define N4 (N_COLS / 4)                 // 65536 float4 per row
#define THREADS 512
#define V4_PER_THREAD 4                 // 16 elements per thread per array
#define F4_PER_BLOCK (THREADS * V4_PER_THREAD)          // 2048 float4
#define BLOCKS_PER_ROW (N4 / F4_PER_BLOCK)              // 32
#define TOTAL_BLOCKS (B_ROWS * BLOCKS_PER_ROW)          // 2048

// Per-block partial: (sum_t, sum t*log2(p), sum (1-t)*log2(1-p), pad).
// Every slot overwritten unconditionally each launch -> no zeroing needed.
__device__ float4 g_part[TOTAL_BLOCKS];
__device__ unsigned int g_count;        // zero-init at load; reset by last block

__global__ __launch_bounds__(THREADS) void bce_fused_kernel(
    const float4* __restrict__ p4, const float4* __restrict__ t4,
    float* __restrict__ out) {
    const int row = blockIdx.y;
    const int chunk = blockIdx.x;
    const int tid = threadIdx.x;
    const long base = (long)row * N4 + (long)chunk * F4_PER_BLOCK + tid;

    // Front-batch all loads for MLP
    float4 pv[V4_PER_THREAD], tv[V4_PER_THREAD];
#pragma unroll
    for (int v = 0; v < V4_PER_THREAD; v++) {
        pv[v] = p4[base + (long)v * THREADS];
        tv[v] = t4[base + (long)v * THREADS];
    }

    float st = 0.f, s1 = 0.f, s2 = 0.f;
#pragma unroll
    for (int v = 0; v < V4_PER_THREAD; v++) {
        const float pe[4] = {pv[v].x, pv[v].y, pv[v].z, pv[v].w};
        const float te[4] = {tv[v].x, tv[v].y, tv[v].z, tv[v].w};
#pragma unroll
        for (int e = 0; e < 4; e++) {
            float lp = __log2f(pe[e]);           // scaled by ln2 in finalize
            float lq = __log2f(1.0f - pe[e]);
            st += te[e];
            s1 = fmaf(te[e], lp, s1);
            s2 += fmaf(-te[e], lq, lq);          // (1-t)*log2(1-p)
        }
    }

    // warp reduce
#pragma unroll
    for (int o = 16; o > 0; o >>= 1) {
        st += __shfl_down_sync(0xFFFFFFFFu, st, o);
        s1 += __shfl_down_sync(0xFFFFFFFFu, s1, o);
        s2 += __shfl_down_sync(0xFFFFFFFFu, s2, o);
    }

    __shared__ float sh_st[THREADS / 32], sh_s1[THREADS / 32], sh_s2[THREADS / 32];
    const int warp = tid >> 5;
    const int lane = tid & 31;
    if (lane == 0) { sh_st[warp] = st; sh_s1[warp] = s1; sh_s2[warp] = s2; }
    __syncthreads();

    if (warp == 0) {
        const int nw = THREADS / 32;   // 16
        float a = (lane < nw) ? sh_st[lane] : 0.f;
        float b = (lane < nw) ? sh_s1[lane] : 0.f;
        float c = (lane < nw) ? sh_s2[lane] : 0.f;
#pragma unroll
        for (int o = 8; o > 0; o >>= 1) {
            a += __shfl_down_sync(0xFFFFFFFFu, a, o);
            b += __shfl_down_sync(0xFFFFFFFFu, b, o);
            c += __shfl_down_sync(0xFFFFFFFFu, c, o);
        }
        if (lane == 0)
            g_part[row * BLOCKS_PER_ROW + chunk] = make_float4(a, b, c, 0.f);
    }

    // ---- last-block-done detection ----
    __shared__ int is_last;
    __threadfence();                   // make g_part visible chip-wide
    if (tid == 0) {
        unsigned int prev = atomicAdd(&g_count, 1u);
        is_last = (prev == TOTAL_BLOCKS - 1u) ? 1 : 0;
    }
    __syncthreads();
    if (!is_last) return;

    // ---- finalize (runs in exactly one block; partials are L2-hot) ----
    // 8 threads per row x 64 rows = 512 threads.
    {
        const int r = tid >> 3;        // 0..63
        const int sub = tid & 7;       // 0..7

        float a = 0.f, b = 0.f, c = 0.f;
#pragma unroll
        for (int k = 0; k < BLOCKS_PER_ROW / 8; k++) {   // 4 iters
            float4 v = g_part[r * BLOCKS_PER_ROW + sub + k * 8];
            a += v.x; b += v.y; c += v.z;
        }
#pragma unroll
        for (int o = 4; o > 0; o >>= 1) {
            a += __shfl_down_sync(0xFFFFFFFFu, a, o, 8);
            b += __shfl_down_sync(0xFFFFFFFFu, b, o, 8);
            c += __shfl_down_sync(0xFFFFFFFFu, c, o, 8);
        }

        __shared__ double sh_row[B_ROWS];
        if (sub == 0) {
            const double LN2 = 0.6931471805599453;
            double beta = 1.0 - (double)a / (double)N_COLS;
            sh_row[r] = (beta * (double)b + (1.0 - beta) * (double)c) * LN2;
        }
        __syncthreads();

        if (tid < 64) {
            double s = sh_row[tid];
#pragma unroll
            for (int o = 16; o > 0; o >>= 1)
                s += __shfl_down_sync(0xFFFFFFFFu, s, o);
            __shared__ double sh2[2];
            if ((tid & 31) == 0) sh2[tid >> 5] = s;
            __syncthreads();
            if (tid == 0) {
                out[0] = (float)(-(sh2[0] + sh2[1]));
                *((volatile unsigned int*)&g_count) = 0u;  // reset for next replay
            }
        }
    }
}

extern "C" void kernel_launch(void* const* d_in, const int* in_sizes, int n_in,
                              void* d_out, int out_size) {
    const float4* p = (const float4*)d_in[0];  // input (probabilities)
    const float4* t = (const float4*)d_in[1];  // target
    float* out = (float*)d_out;

    dim3 grid(BLOCKS_PER_ROW, B_ROWS);
    bce_fused_kernel<<<grid, THREADS>>>(p, t, out);
}

// round 6
// speedup vs baseline: 1.0011x; 1.0011x over previous
#include <cuda_runtime.h>

// Problem constants
#define B_ROWS 64
#define N_COLS 262144
#define N4 (N_COLS / 4)                 // 65536 float4 per row
#define THREADS 256
#define V4_PER_THREAD 4                 // 16 elements per thread per array
#define F4_PER_BLOCK (THREADS * V4_PER_THREAD)          // 1024 float4
#define BLOCKS_PER_ROW (N4 / F4_PER_BLOCK)              // 64
#define TOTAL_BLOCKS (B_ROWS * BLOCKS_PER_ROW)          // 4096

// Per-block partial: (sum_t, sum t*log2(p), sum (1-t)*log2(1-p), pad).
// Every slot overwritten unconditionally each launch -> no zeroing needed.
__device__ float4 g_part[TOTAL_BLOCKS];
__device__ unsigned int g_count;        // zero-init at load; reset by last block

// Release+acquire counter bump: orders this block's g_part store (release) and,
// for the last arriver, makes all other blocks' partials visible (acquire).
// One L2 atomic instead of MEMBAR.ALL.GPU (+CCTL.IVALL) + ATOMG.
__device__ __forceinline__ unsigned int arrive_acq_rel(unsigned int* ctr) {
    unsigned int prev;
    asm volatile("atom.add.acq_rel.gpu.u32 %0, [%1], 1;"
                 : "=r"(prev) : "l"(ctr) : "memory");
    return prev;
}

__global__ __launch_bounds__(THREADS) void bce_fused_kernel(
    const float4* __restrict__ p4, const float4* __restrict__ t4,
    float* __restrict__ out) {
    const int row = blockIdx.y;
    const int chunk = blockIdx.x;
    const int tid = threadIdx.x;
    const long base = (long)row * N4 + (long)chunk * F4_PER_BLOCK + tid;

    // Front-batch all loads for MLP
    float4 pv[V4_PER_THREAD], tv[V4_PER_THREAD];
#pragma unroll
    for (int v = 0; v < V4_PER_THREAD; v++) {
        pv[v] = p4[base + (long)v * THREADS];
        tv[v] = t4[base + (long)v * THREADS];
    }

    float st = 0.f, s1 = 0.f, s2 = 0.f;
#pragma unroll
    for (int v = 0; v < V4_PER_THREAD; v++) {
        const float pe[4] = {pv[v].x, pv[v].y, pv[v].z, pv[v].w};
        const float te[4] = {tv[v].x, tv[v].y, tv[v].z, tv[v].w};
#pragma unroll
        for (int e = 0; e < 4; e++) {
            float lp = __log2f(pe[e]);           // scaled by ln2 in finalize
            float lq = __log2f(1.0f - pe[e]);
            st += te[e];
            s1 = fmaf(te[e], lp, s1);
            s2 += fmaf(-te[e], lq, lq);          // (1-t)*log2(1-p)
        }
    }

    // warp reduce
#pragma unroll
    for (int o = 16; o > 0; o >>= 1) {
        st += __shfl_down_sync(0xFFFFFFFFu, st, o);
        s1 += __shfl_down_sync(0xFFFFFFFFu, s1, o);
        s2 += __shfl_down_sync(0xFFFFFFFFu, s2, o);
    }

    __shared__ float sh_st[THREADS / 32], sh_s1[THREADS / 32], sh_s2[THREADS / 32];
    const int warp = tid >> 5;
    const int lane = tid & 31;
    if (lane == 0) { sh_st[warp] = st; sh_s1[warp] = s1; sh_s2[warp] = s2; }
    __syncthreads();

    if (warp == 0) {
        const int nw = THREADS / 32;   // 8
        float a = (lane < nw) ? sh_st[lane] : 0.f;
        float b = (lane < nw) ? sh_s1[lane] : 0.f;
        float c = (lane < nw) ? sh_s2[lane] : 0.f;
#pragma unroll
        for (int o = 4; o > 0; o >>= 1) {
            a += __shfl_down_sync(0xFFFFFFFFu, a, o);
            b += __shfl_down_sync(0xFFFFFFFFu, b, o);
            c += __shfl_down_sync(0xFFFFFFFFu, c, o);
        }
        if (lane == 0)
            g_part[row * BLOCKS_PER_ROW + chunk] = make_float4(a, b, c, 0.f);
    }

    // ---- last-block-done detection (release/acquire, no full fence) ----
    __shared__ int is_last;
    __syncthreads();                   // g_part store issued before arrival
    if (tid == 0)
        is_last = (arrive_acq_rel(&g_count) == TOTAL_BLOCKS - 1u) ? 1 : 0;
    __syncthreads();
    if (!is_last) return;

    // ---- finalize in the last block (partials are L2-hot) ----
    // 4 threads per row x 64 rows = 256 threads; 16 partials per thread.
    {
        const int r = tid >> 2;        // 0..63
        const int sub = tid & 3;       // 0..3

        float a = 0.f, b = 0.f, c = 0.f;
#pragma unroll
        for (int k = 0; k < BLOCKS_PER_ROW / 4; k++) {   // 16 iters
            float4 v = g_part[r * BLOCKS_PER_ROW + sub + k * 4];
            a += v.x; b += v.y; c += v.z;
        }
#pragma unroll
        for (int o = 2; o > 0; o >>= 1) {
            a += __shfl_down_sync(0xFFFFFFFFu, a, o, 4);
            b += __shfl_down_sync(0xFFFFFFFFu, b, o, 4);
            c += __shfl_down_sync(0xFFFFFFFFu, c, o, 4);
        }

        __shared__ double sh_row[B_ROWS];
        if (sub == 0) {
            const double LN2 = 0.6931471805599453;
            double beta = 1.0 - (double)a / (double)N_COLS;
            sh_row[r] = (beta * (double)b + (1.0 - beta) * (double)c) * LN2;
        }
        __syncthreads();

        if (tid < 64) {
            double s = sh_row[tid];
#pragma unroll
            for (int o = 16; o > 0; o >>= 1)
                s += __shfl_down_sync(0xFFFFFFFFu, s, o);
            __shared__ double sh2[2];
            if ((tid & 31) == 0) sh2[tid >> 5] = s;
            __syncthreads();
            if (tid == 0) {
                out[0] = (float)(-(sh2[0] + sh2[1]));
                *((volatile unsigned int*)&g_count) = 0u;  // reset for next replay
            }
        }
    }
}

extern "C" void kernel_launch(void* const* d_in, const int* in_sizes, int n_in,
                              void* d_out, int out_size) {
    const float4* p = (const float4*)d_in[0];  // input (probabilities)
    const float4* t = (const float4*)d_in[1];  // target
    float* out = (float*)d_out;

    dim3 grid(BLOCKS_PER_ROW, B_ROWS);
    bce_fused_kernel<<<grid, THREADS>>>(p, t, out);
}